// round 3
// baseline (speedup 1.0000x reference)
#include <cuda_runtime.h>

// Problem constants
#define BB 8
#define NN 16384
#define CC 256
#define DD 2
#define KSEG 4096
#define FDIM 258            // C + D
#define FP 264              // padded to multiple of 8 (GEMM K)
#define MROWS (BB*KSEG)     // 32768 cluster rows
#define NPTS  (BB*NN)       // 131072 points
#define NOUT  (2*CC)        // 512

#define POS_OFF  0
#define FEAT_OFF (MROWS*DD)                 // 65536
#define MASK_OFF (FEAT_OFF + MROWS*NOUT)    // 16842752

// ---------------- scratch (device globals; no runtime allocation) -----------
__device__ unsigned int g_posmax[2];
__device__ float g_cnt[MROWS];
__device__ float g_sumpos[MROWS * 2];
__device__ float g_meanpos[MROWS * 2];
__device__ float g_scale[MROWS];            // valid / safe_count
__device__ float g_S[(size_t)MROWS * FP];   // per-cluster sum of ln(x), padded
__device__ float g_Wp[NOUT * FP];           // lin_w zero-padded to FP cols

// ---------------- kernel 0: zero scratch ------------------------------------
__global__ void k_zero() {
    int i = blockIdx.x * blockDim.x + threadIdx.x;
    int stride = gridDim.x * blockDim.x;
    float4 z = make_float4(0.f, 0.f, 0.f, 0.f);
    float4* S4 = reinterpret_cast<float4*>(g_S);
    const int n4 = (MROWS * FP) / 4;
    for (int j = i; j < n4; j += stride) S4[j] = z;
    for (int j = i; j < MROWS; j += stride) g_cnt[j] = 0.f;
    for (int j = i; j < MROWS * 2; j += stride) g_sumpos[j] = 0.f;
    if (i < 2) g_posmax[i] = 0u;
}

// ---------------- kernel 1: global per-dim max of pos ------------------------
__global__ void k_posmax(const float2* __restrict__ pos) {
    int i = blockIdx.x * blockDim.x + threadIdx.x;
    int stride = gridDim.x * blockDim.x;
    float mx = 0.f, my = 0.f;
    for (int p = i; p < NPTS; p += stride) {
        float2 v = pos[p];
        mx = fmaxf(mx, v.x);
        my = fmaxf(my, v.y);
    }
#pragma unroll
    for (int o = 16; o; o >>= 1) {
        mx = fmaxf(mx, __shfl_xor_sync(0xffffffffu, mx, o));
        my = fmaxf(my, __shfl_xor_sync(0xffffffffu, my, o));
    }
    if ((threadIdx.x & 31) == 0) {
        atomicMax(&g_posmax[0], __float_as_uint(mx));   // pos >= 0, bit order == value order
        atomicMax(&g_posmax[1], __float_as_uint(my));
    }
}

// ---------------- kernel 2: counts + raw pos sums per segment ----------------
__global__ void k_count(const float2* __restrict__ pos, const int* __restrict__ asg) {
    int p = blockIdx.x * blockDim.x + threadIdx.x;
    if (p >= NPTS) return;
    int b = p >> 14;                       // N = 16384
    int seg = (b << 12) + asg[p];          // K = 4096
    float2 pp = pos[p];
    atomicAdd(&g_cnt[seg], 1.0f);
    atomicAdd(&g_sumpos[2 * seg], pp.x);
    atomicAdd(&g_sumpos[2 * seg + 1], pp.y);
}

// ---------------- kernel 3: mean pos, scale, write new_pos + mask ------------
__global__ void k_meanpos(float* __restrict__ out) {
    int i = blockIdx.x * blockDim.x + threadIdx.x;
    if (i >= MROWS) return;
    float c = g_cnt[i];
    float safe = fmaxf(c, 1.0f);
    float valid = (c > 0.f) ? 1.0f : 0.0f;
    float invmx = 1.0f / __uint_as_float(g_posmax[0]);
    float invmy = 1.0f / __uint_as_float(g_posmax[1]);
    float mx = g_sumpos[2 * i]     * invmx / safe;   // mean of normalized pos
    float my = g_sumpos[2 * i + 1] * invmy / safe;
    g_meanpos[2 * i] = mx;
    g_meanpos[2 * i + 1] = my;
    g_scale[i] = valid / safe;
    out[POS_OFF + 2 * i]     = mx * valid;
    out[POS_OFF + 2 * i + 1] = my * valid;
    out[MASK_OFF + i] = valid;
}

// ---------------- kernel: pad lin_w into g_Wp --------------------------------
__global__ void k_wp(const float* __restrict__ lw) {
    int i = blockIdx.x * blockDim.x + threadIdx.x;
    if (i >= NOUT * FP) return;
    int row = i / FP;
    int col = i - row * FP;
    g_Wp[i] = (col < FDIM) ? lw[row * FDIM + col] : 0.0f;
}

// ---------------- kernel 4: per-point layernorm + vector scatter -------------
// One warp per point. Lane l owns feat dims [8l, 8l+8); lane 0 also owns rel_pos.
__global__ __launch_bounds__(256) void k_scatter(
    const float2* __restrict__ pos, const float4* __restrict__ feat4,
    const int* __restrict__ asg,
    const float* __restrict__ nw, const float* __restrict__ nb)
{
    int gtid = blockIdx.x * blockDim.x + threadIdx.x;
    int wid = gtid >> 5;
    int lane = threadIdx.x & 31;
    if (wid >= NPTS) return;

    int b = wid >> 14;
    int seg = (b << 12) + asg[wid];

    // feat row: 64 float4, lane gets 2 consecutive ones (coalesced)
    const float4* fp = feat4 + (size_t)wid * 64 + lane * 2;
    float4 f0 = fp[0];
    float4 f1 = fp[1];

    float invmx = 1.0f / __uint_as_float(g_posmax[0]);
    float invmy = 1.0f / __uint_as_float(g_posmax[1]);
    float2 pp = pos[wid];
    float rx = pp.x * invmx - g_meanpos[2 * seg];
    float ry = pp.y * invmy - g_meanpos[2 * seg + 1];

    float s = f0.x + f0.y + f0.z + f0.w + f1.x + f1.y + f1.z + f1.w;
    float q = f0.x * f0.x + f0.y * f0.y + f0.z * f0.z + f0.w * f0.w
            + f1.x * f1.x + f1.y * f1.y + f1.z * f1.z + f1.w * f1.w;
    if (lane == 0) {
        s += rx + ry;
        q += rx * rx + ry * ry;
    }
#pragma unroll
    for (int o = 16; o; o >>= 1) {
        s += __shfl_xor_sync(0xffffffffu, s, o);
        q += __shfl_xor_sync(0xffffffffu, q, o);
    }
    const float rn = 1.0f / 258.0f;
    float mu = s * rn;
    float var = q * rn - mu * mu;
    float inv = rsqrtf(var + 1e-5f);

    const float4* nw4 = reinterpret_cast<const float4*>(nw);
    const float4* nb4 = reinterpret_cast<const float4*>(nb);
    float4 w0 = nw4[lane * 2], w1 = nw4[lane * 2 + 1];
    float4 bb0 = nb4[lane * 2], bb1 = nb4[lane * 2 + 1];

    float4 v0, v1;
    v0.x = (f0.x - mu) * inv * w0.x + bb0.x;
    v0.y = (f0.y - mu) * inv * w0.y + bb0.y;
    v0.z = (f0.z - mu) * inv * w0.z + bb0.z;
    v0.w = (f0.w - mu) * inv * w0.w + bb0.w;
    v1.x = (f1.x - mu) * inv * w1.x + bb1.x;
    v1.y = (f1.y - mu) * inv * w1.y + bb1.y;
    v1.z = (f1.z - mu) * inv * w1.z + bb1.z;
    v1.w = (f1.w - mu) * inv * w1.w + bb1.w;

    float* dst = g_S + (size_t)seg * FP + lane * 8;
    asm volatile("red.global.add.v4.f32 [%0], {%1,%2,%3,%4};"
                 :: "l"(dst), "f"(v0.x), "f"(v0.y), "f"(v0.z), "f"(v0.w) : "memory");
    asm volatile("red.global.add.v4.f32 [%0], {%1,%2,%3,%4};"
                 :: "l"(dst + 4), "f"(v1.x), "f"(v1.y), "f"(v1.z), "f"(v1.w) : "memory");
    if (lane == 0) {
        float lx = (rx - mu) * inv * nw[256] + nb[256];
        float ly = (ry - mu) * inv * nw[257] + nb[257];
        asm volatile("red.global.add.v2.f32 [%0], {%1,%2};"
                     :: "l"(g_S + (size_t)seg * FP + 256), "f"(lx), "f"(ly) : "memory");
    }
}

// ---------------- kernel 5: GEMM  out[m,o] = (S[m,:].W[o,:]) * scale[m] ------
// 128x128 tile, BK=8, 256 threads, 8x8 micro-tile per thread.
__global__ __launch_bounds__(256) void k_gemm(float* __restrict__ outfeat) {
    __shared__ float As[8][128];
    __shared__ float Bs[8][128];
    const int tid = threadIdx.x;
    const int bm = blockIdx.y * 128;
    const int bn = blockIdx.x * 128;
    const int lrow = tid >> 1;           // 0..127
    const int lcol = (tid & 1) * 4;      // 0 or 4
    const int tx = tid & 15;             // 0..15
    const int ty = tid >> 4;             // 0..15

    float acc[8][8];
#pragma unroll
    for (int i = 0; i < 8; i++)
#pragma unroll
        for (int j = 0; j < 8; j++) acc[i][j] = 0.f;

    const float* Aptr = g_S + (size_t)(bm + lrow) * FP + lcol;
    const float* Bptr = g_Wp + (size_t)(bn + lrow) * FP + lcol;

    for (int k0 = 0; k0 < FP; k0 += 8) {
        float4 a4 = *reinterpret_cast<const float4*>(Aptr + k0);
        float4 b4 = *reinterpret_cast<const float4*>(Bptr + k0);
        As[lcol + 0][lrow] = a4.x;
        As[lcol + 1][lrow] = a4.y;
        As[lcol + 2][lrow] = a4.z;
        As[lcol + 3][lrow] = a4.w;
        Bs[lcol + 0][lrow] = b4.x;
        Bs[lcol + 1][lrow] = b4.y;
        Bs[lcol + 2][lrow] = b4.z;
        Bs[lcol + 3][lrow] = b4.w;
        __syncthreads();
#pragma unroll
        for (int kk = 0; kk < 8; kk++) {
            float4 a0 = *reinterpret_cast<const float4*>(&As[kk][ty * 8]);
            float4 a1 = *reinterpret_cast<const float4*>(&As[kk][ty * 8 + 4]);
            float4 b0 = *reinterpret_cast<const float4*>(&Bs[kk][tx * 8]);
            float4 b1 = *reinterpret_cast<const float4*>(&Bs[kk][tx * 8 + 4]);
            float ar[8] = {a0.x, a0.y, a0.z, a0.w, a1.x, a1.y, a1.z, a1.w};
            float br[8] = {b0.x, b0.y, b0.z, b0.w, b1.x, b1.y, b1.z, b1.w};
#pragma unroll
            for (int i = 0; i < 8; i++)
#pragma unroll
                for (int j = 0; j < 8; j++)
                    acc[i][j] = fmaf(ar[i], br[j], acc[i][j]);
        }
        __syncthreads();
    }

#pragma unroll
    for (int i = 0; i < 8; i++) {
        int row = bm + ty * 8 + i;
        float sc = g_scale[row];
        float4 o0 = make_float4(acc[i][0] * sc, acc[i][1] * sc, acc[i][2] * sc, acc[i][3] * sc);
        float4 o1 = make_float4(acc[i][4] * sc, acc[i][5] * sc, acc[i][6] * sc, acc[i][7] * sc);
        float* op = outfeat + (size_t)row * NOUT + bn + tx * 8;
        *reinterpret_cast<float4*>(op) = o0;
        *reinterpret_cast<float4*>(op + 4) = o1;
    }
}

// ---------------- launch ------------------------------------------------------
extern "C" void kernel_launch(void* const* d_in, const int* in_sizes, int n_in,
                              void* d_out, int out_size) {
    const float* pos  = (const float*)d_in[0];
    const float* feat = (const float*)d_in[1];
    const int*   asg  = (const int*)d_in[2];
    const float* nw   = (const float*)d_in[3];
    const float* nb   = (const float*)d_in[4];
    const float* lw   = (const float*)d_in[5];
    float* out = (float*)d_out;

    k_zero<<<4096, 256>>>();
    k_posmax<<<256, 256>>>((const float2*)pos);
    k_count<<<(NPTS + 255) / 256, 256>>>((const float2*)pos, asg);
    k_meanpos<<<(MROWS + 255) / 256, 256>>>(out);
    k_wp<<<(NOUT * FP + 255) / 256, 256>>>(lw);
    k_scatter<<<NPTS / 8, 256>>>((const float2*)pos, (const float4*)feat, asg, nw, nb);
    dim3 g(NOUT / 128, MROWS / 128);
    k_gemm<<<g, 256>>>(out + FEAT_OFF);
}

// round 5
// speedup vs baseline: 2.0460x; 2.0460x over previous
#include <cuda_runtime.h>
#include <cstdint>

// Problem constants
#define BB 8
#define NN 16384
#define CC 256
#define DD 2
#define KSEG 4096
#define FDIM 258            // C + D
#define FP 288              // padded K: 9 chunks of 32
#define NCH 9               // FP / 32
#define MROWS (BB*KSEG)     // 32768 cluster rows
#define NPTS  (BB*NN)       // 131072 points
#define NOUT  (2*CC)        // 512

#define POS_OFF  0
#define FEAT_OFF (MROWS*DD)                 // 65536
#define MASK_OFF (FEAT_OFF + MROWS*NOUT)    // 16842752

// GEMM tile
#define BM 128
#define BN 128
#define BK 32
#define LDA 36              // BK + 4 padding (floats) -> conflict-free frags

// ---------------- scratch (device globals; no runtime allocation) -----------
__device__ unsigned int g_posmax[2];
__device__ float g_cnt[MROWS];
__device__ float g_sumpos[MROWS * 2];
__device__ float g_meanpos[MROWS * 2];
__device__ float g_scale[MROWS];            // valid / safe_count
__device__ float g_S[(size_t)MROWS * FP];   // per-cluster sum of ln(x), padded
__device__ float g_Wp[NOUT * FP];           // lin_w zero-padded to FP cols

__device__ __forceinline__ uint32_t f2tf32(float x) {
    uint32_t r; asm("cvt.rna.tf32.f32 %0, %1;" : "=r"(r) : "f"(x)); return r;
}

// ---------------- kernel 0: zero scratch ------------------------------------
__global__ void k_zero() {
    int i = blockIdx.x * blockDim.x + threadIdx.x;
    int stride = gridDim.x * blockDim.x;
    float4 z = make_float4(0.f, 0.f, 0.f, 0.f);
    float4* S4 = reinterpret_cast<float4*>(g_S);
    const int n4 = (MROWS * FP) / 4;
    for (int j = i; j < n4; j += stride) S4[j] = z;
    for (int j = i; j < MROWS; j += stride) g_cnt[j] = 0.f;
    for (int j = i; j < MROWS * 2; j += stride) g_sumpos[j] = 0.f;
    if (i < 2) g_posmax[i] = 0u;
}

// ---------------- kernel 1: global per-dim max of pos ------------------------
__global__ void k_posmax(const float2* __restrict__ pos) {
    int i = blockIdx.x * blockDim.x + threadIdx.x;
    int stride = gridDim.x * blockDim.x;
    float mx = 0.f, my = 0.f;
    for (int p = i; p < NPTS; p += stride) {
        float2 v = pos[p];
        mx = fmaxf(mx, v.x);
        my = fmaxf(my, v.y);
    }
#pragma unroll
    for (int o = 16; o; o >>= 1) {
        mx = fmaxf(mx, __shfl_xor_sync(0xffffffffu, mx, o));
        my = fmaxf(my, __shfl_xor_sync(0xffffffffu, my, o));
    }
    if ((threadIdx.x & 31) == 0) {
        atomicMax(&g_posmax[0], __float_as_uint(mx));   // pos >= 0: bit order == value order
        atomicMax(&g_posmax[1], __float_as_uint(my));
    }
}

// ---------------- kernel 2: counts + raw pos sums per segment ----------------
__global__ void k_count(const float2* __restrict__ pos, const int* __restrict__ asg) {
    int p = blockIdx.x * blockDim.x + threadIdx.x;
    if (p >= NPTS) return;
    int b = p >> 14;
    int seg = (b << 12) + asg[p];
    float2 pp = pos[p];
    atomicAdd(&g_cnt[seg], 1.0f);
    atomicAdd(&g_sumpos[2 * seg], pp.x);
    atomicAdd(&g_sumpos[2 * seg + 1], pp.y);
}

// ---------------- kernel 3: mean pos, scale, write new_pos + mask ------------
__global__ void k_meanpos(float* __restrict__ out) {
    int i = blockIdx.x * blockDim.x + threadIdx.x;
    if (i >= MROWS) return;
    float c = g_cnt[i];
    float safe = fmaxf(c, 1.0f);
    float valid = (c > 0.f) ? 1.0f : 0.0f;
    float invmx = 1.0f / __uint_as_float(g_posmax[0]);
    float invmy = 1.0f / __uint_as_float(g_posmax[1]);
    float mx = g_sumpos[2 * i]     * invmx / safe;
    float my = g_sumpos[2 * i + 1] * invmy / safe;
    g_meanpos[2 * i] = mx;
    g_meanpos[2 * i + 1] = my;
    g_scale[i] = valid / safe;
    out[POS_OFF + 2 * i]     = mx * valid;
    out[POS_OFF + 2 * i + 1] = my * valid;
    out[MASK_OFF + i] = valid;
}

// ---------------- kernel: pad lin_w into g_Wp --------------------------------
__global__ void k_wp(const float* __restrict__ lw) {
    int i = blockIdx.x * blockDim.x + threadIdx.x;
    if (i >= NOUT * FP) return;
    int row = i / FP;
    int col = i - row * FP;
    g_Wp[i] = (col < FDIM) ? lw[row * FDIM + col] : 0.0f;
}

// ---------------- kernel 4: per-point layernorm + vector scatter -------------
__global__ __launch_bounds__(256) void k_scatter(
    const float2* __restrict__ pos, const float4* __restrict__ feat4,
    const int* __restrict__ asg,
    const float* __restrict__ nw, const float* __restrict__ nb)
{
    int gtid = blockIdx.x * blockDim.x + threadIdx.x;
    int wid = gtid >> 5;
    int lane = threadIdx.x & 31;
    if (wid >= NPTS) return;

    int b = wid >> 14;
    int seg = (b << 12) + asg[wid];

    const float4* fp = feat4 + (size_t)wid * 64 + lane * 2;
    float4 f0 = fp[0];
    float4 f1 = fp[1];

    float invmx = 1.0f / __uint_as_float(g_posmax[0]);
    float invmy = 1.0f / __uint_as_float(g_posmax[1]);
    float2 pp = pos[wid];
    float rx = pp.x * invmx - g_meanpos[2 * seg];
    float ry = pp.y * invmy - g_meanpos[2 * seg + 1];

    float s = f0.x + f0.y + f0.z + f0.w + f1.x + f1.y + f1.z + f1.w;
    float q = f0.x * f0.x + f0.y * f0.y + f0.z * f0.z + f0.w * f0.w
            + f1.x * f1.x + f1.y * f1.y + f1.z * f1.z + f1.w * f1.w;
    if (lane == 0) {
        s += rx + ry;
        q += rx * rx + ry * ry;
    }
#pragma unroll
    for (int o = 16; o; o >>= 1) {
        s += __shfl_xor_sync(0xffffffffu, s, o);
        q += __shfl_xor_sync(0xffffffffu, q, o);
    }
    const float rn = 1.0f / 258.0f;
    float mu = s * rn;
    float var = q * rn - mu * mu;
    float inv = rsqrtf(var + 1e-5f);

    const float4* nw4 = reinterpret_cast<const float4*>(nw);
    const float4* nb4 = reinterpret_cast<const float4*>(nb);
    float4 w0 = nw4[lane * 2], w1 = nw4[lane * 2 + 1];
    float4 bb0 = nb4[lane * 2], bb1 = nb4[lane * 2 + 1];

    float4 v0, v1;
    v0.x = (f0.x - mu) * inv * w0.x + bb0.x;
    v0.y = (f0.y - mu) * inv * w0.y + bb0.y;
    v0.z = (f0.z - mu) * inv * w0.z + bb0.z;
    v0.w = (f0.w - mu) * inv * w0.w + bb0.w;
    v1.x = (f1.x - mu) * inv * w1.x + bb1.x;
    v1.y = (f1.y - mu) * inv * w1.y + bb1.y;
    v1.z = (f1.z - mu) * inv * w1.z + bb1.z;
    v1.w = (f1.w - mu) * inv * w1.w + bb1.w;

    float* dst = g_S + (size_t)seg * FP + lane * 8;
    asm volatile("red.global.add.v4.f32 [%0], {%1,%2,%3,%4};"
                 :: "l"(dst), "f"(v0.x), "f"(v0.y), "f"(v0.z), "f"(v0.w) : "memory");
    asm volatile("red.global.add.v4.f32 [%0], {%1,%2,%3,%4};"
                 :: "l"(dst + 4), "f"(v1.x), "f"(v1.y), "f"(v1.z), "f"(v1.w) : "memory");
    if (lane == 0) {
        float lx = (rx - mu) * inv * nw[256] + nb[256];
        float ly = (ry - mu) * inv * nw[257] + nb[257];
        asm volatile("red.global.add.v2.f32 [%0], {%1,%2};"
                     :: "l"(g_S + (size_t)seg * FP + 256), "f"(lx), "f"(ly) : "memory");
    }
}

// ---------------- kernel 5: tf32 mma.sync GEMM --------------------------------
// out[m,o] = (S[m,:].Wp[o,:]) * scale[m]
// 128x128 tile, BK=32, 256 threads = 8 warps in 4(M) x 2(N); warp tile 32x64.
// Register double-buffer on the global feed, conflict-free padded smem.
__global__ __launch_bounds__(256) void k_gemm_mma(float* __restrict__ outfeat) {
    __shared__ uint32_t As[BM * LDA];
    __shared__ uint32_t Bs[BN * LDA];

    const int tid = threadIdx.x;
    const int lane = tid & 31;
    const int warp = tid >> 5;
    const int wm = warp & 3;       // warp M index (0..3)
    const int wn = warp >> 2;      // warp N index (0..1)
    const int bm = blockIdx.y * BM;
    const int bn = blockIdx.x * BN;

    const int grow = tid >> 3;     // base row for global loads (uses v = tid + it*256)
    const int gk4  = tid & 7;      // float4 index within 32-wide chunk

    uint32_t apf[4][4], bpf[4][4];

    auto loadA = [&](int c) {
#pragma unroll
        for (int it = 0; it < 4; it++) {
            int row = grow + it * 32;
            float4 x = *reinterpret_cast<const float4*>(
                g_S + (size_t)(bm + row) * FP + c * BK + gk4 * 4);
            apf[it][0] = f2tf32(x.x); apf[it][1] = f2tf32(x.y);
            apf[it][2] = f2tf32(x.z); apf[it][3] = f2tf32(x.w);
        }
    };
    auto loadB = [&](int c) {
#pragma unroll
        for (int it = 0; it < 4; it++) {
            int row = grow + it * 32;
            float4 x = *reinterpret_cast<const float4*>(
                g_Wp + (size_t)(bn + row) * FP + c * BK + gk4 * 4);
            bpf[it][0] = f2tf32(x.x); bpf[it][1] = f2tf32(x.y);
            bpf[it][2] = f2tf32(x.z); bpf[it][3] = f2tf32(x.w);
        }
    };
    auto stash = [&]() {
#pragma unroll
        for (int it = 0; it < 4; it++) {
            int row = grow + it * 32;
            uint32_t* pa = &As[row * LDA + gk4 * 4];
            pa[0] = apf[it][0]; pa[1] = apf[it][1]; pa[2] = apf[it][2]; pa[3] = apf[it][3];
            uint32_t* pb = &Bs[row * LDA + gk4 * 4];
            pb[0] = bpf[it][0]; pb[1] = bpf[it][1]; pb[2] = bpf[it][2]; pb[3] = bpf[it][3];
        }
    };

    float acc[2][8][4];
#pragma unroll
    for (int mt = 0; mt < 2; mt++)
#pragma unroll
        for (int nt = 0; nt < 8; nt++)
#pragma unroll
            for (int q = 0; q < 4; q++) acc[mt][nt][q] = 0.f;

    loadA(0); loadB(0);
    stash();
    __syncthreads();

    const int qid = lane >> 2;     // 0..7
    const int tig = lane & 3;      // 0..3

    for (int c = 0; c < NCH; c++) {
        if (c + 1 < NCH) { loadA(c + 1); loadB(c + 1); }

#pragma unroll
        for (int k8 = 0; k8 < 4; k8++) {
            const int kb = k8 * 8;
            uint32_t af[2][4];
#pragma unroll
            for (int mt = 0; mt < 2; mt++) {
                int r = wm * 32 + mt * 16 + qid;
                int ci = kb + tig;
                af[mt][0] = As[r * LDA + ci];
                af[mt][1] = As[(r + 8) * LDA + ci];
                af[mt][2] = As[r * LDA + ci + 4];
                af[mt][3] = As[(r + 8) * LDA + ci + 4];
            }
            uint32_t bf[8][2];
#pragma unroll
            for (int nt = 0; nt < 8; nt++) {
                int n = wn * 64 + nt * 8 + qid;
                int kk = kb + tig;
                bf[nt][0] = Bs[n * LDA + kk];
                bf[nt][1] = Bs[n * LDA + kk + 4];
            }
#pragma unroll
            for (int mt = 0; mt < 2; mt++)
#pragma unroll
                for (int nt = 0; nt < 8; nt++) {
                    asm volatile(
                        "mma.sync.aligned.m16n8k8.row.col.f32.tf32.tf32.f32 "
                        "{%0,%1,%2,%3}, {%4,%5,%6,%7}, {%8,%9}, {%0,%1,%2,%3};"
                        : "+f"(acc[mt][nt][0]), "+f"(acc[mt][nt][1]),
                          "+f"(acc[mt][nt][2]), "+f"(acc[mt][nt][3])
                        : "r"(af[mt][0]), "r"(af[mt][1]), "r"(af[mt][2]), "r"(af[mt][3]),
                          "r"(bf[nt][0]), "r"(bf[nt][1]));
                }
        }
        __syncthreads();
        if (c + 1 < NCH) {
            stash();
            __syncthreads();
        }
    }

    // epilogue: scale by g_scale[row], store float2 per (row, n-tile)
#pragma unroll
    for (int mt = 0; mt < 2; mt++) {
        int r0 = bm + wm * 32 + mt * 16 + qid;
        float s0 = g_scale[r0];
        float s1 = g_scale[r0 + 8];
        float* row0 = outfeat + (size_t)r0 * NOUT + bn + wn * 64 + tig * 2;
        float* row1 = outfeat + (size_t)(r0 + 8) * NOUT + bn + wn * 64 + tig * 2;
#pragma unroll
        for (int nt = 0; nt < 8; nt++) {
            float2 o0 = make_float2(acc[mt][nt][0] * s0, acc[mt][nt][1] * s0);
            float2 o1 = make_float2(acc[mt][nt][2] * s1, acc[mt][nt][3] * s1);
            *reinterpret_cast<float2*>(row0 + nt * 8) = o0;
            *reinterpret_cast<float2*>(row1 + nt * 8) = o1;
        }
    }
}

// ---------------- launch ------------------------------------------------------
extern "C" void kernel_launch(void* const* d_in, const int* in_sizes, int n_in,
                              void* d_out, int out_size) {
    const float* pos  = (const float*)d_in[0];
    const float* feat = (const float*)d_in[1];
    const int*   asg  = (const int*)d_in[2];
    const float* nw   = (const float*)d_in[3];
    const float* nb   = (const float*)d_in[4];
    const float* lw   = (const float*)d_in[5];
    float* out = (float*)d_out;

    k_zero<<<4096, 256>>>();
    k_posmax<<<256, 256>>>((const float2*)pos);
    k_count<<<(NPTS + 255) / 256, 256>>>((const float2*)pos, asg);
    k_meanpos<<<(MROWS + 255) / 256, 256>>>(out);
    k_wp<<<(NOUT * FP + 255) / 256, 256>>>(lw);
    k_scatter<<<NPTS / 8, 256>>>((const float2*)pos, (const float4*)feat, asg, nw, nb);
    dim3 g(NOUT / BN, MROWS / BM);   // (4, 256)
    k_gemm_mma<<<g, 256>>>(out + FEAT_OFF);
}

// round 6
// speedup vs baseline: 2.1607x; 1.0560x over previous
#include <cuda_runtime.h>
#include <cstdint>

// Problem constants
#define BB 8
#define NN 16384
#define CC 256
#define DD 2
#define KSEG 4096
#define FDIM 258            // C + D
#define FP 288              // padded K: 9 chunks of 32
#define NCH 9               // FP / 32
#define MROWS (BB*KSEG)     // 32768 cluster rows
#define NPTS  (BB*NN)       // 131072 points
#define NOUT  (2*CC)        // 512

#define POS_OFF  0
#define FEAT_OFF (MROWS*DD)                 // 65536
#define MASK_OFF (FEAT_OFF + MROWS*NOUT)    // 16842752

// GEMM tile
#define BM 128
#define BN 128
#define BK 32
#define LDA 36              // BK + 4 padding -> conflict-free frags

// ---------------- scratch (device globals; no runtime allocation) -----------
__device__ unsigned int g_posmax[2];
__device__ float g_cnt[MROWS];
__device__ float g_sumpos[MROWS * 2];
__device__ float g_meanpos[MROWS * 2];
__device__ float g_scale[MROWS];            // valid / safe_count
__device__ int   g_start[MROWS];
__device__ int   g_fill[MROWS];
__device__ int   g_total;
__device__ int   g_idx[NPTS];
__device__ float g_S[(size_t)MROWS * FP];   // per-cluster sum of ln(x), padded
__device__ float g_Wp[NOUT * FP];           // lin_w zero-padded to FP cols

__device__ __forceinline__ uint32_t f2tf32(float x) {
    uint32_t r; asm("cvt.rna.tf32.f32 %0, %1;" : "=r"(r) : "f"(x)); return r;
}

// ---------------- kernel 0: zero small scratch (g_S no longer needs it) ------
__global__ void k_zero() {
    int i = blockIdx.x * blockDim.x + threadIdx.x;
    int stride = gridDim.x * blockDim.x;
    for (int j = i; j < MROWS; j += stride) { g_cnt[j] = 0.f; g_fill[j] = 0; }
    for (int j = i; j < MROWS * 2; j += stride) g_sumpos[j] = 0.f;
    if (i < 2) g_posmax[i] = 0u;
    if (i == 2) g_total = 0;
}

// ---------------- kernel 1: posmax + counts/pos-sums (fused, independent) ----
__global__ void k_init(const float2* __restrict__ pos, const int* __restrict__ asg) {
    if (blockIdx.x < 256) {
        // global per-dim max
        int i = blockIdx.x * 256 + threadIdx.x;
        int stride = 256 * 256;
        float mx = 0.f, my = 0.f;
        for (int p = i; p < NPTS; p += stride) {
            float2 v = pos[p];
            mx = fmaxf(mx, v.x);
            my = fmaxf(my, v.y);
        }
#pragma unroll
        for (int o = 16; o; o >>= 1) {
            mx = fmaxf(mx, __shfl_xor_sync(0xffffffffu, mx, o));
            my = fmaxf(my, __shfl_xor_sync(0xffffffffu, my, o));
        }
        if ((threadIdx.x & 31) == 0) {
            atomicMax(&g_posmax[0], __float_as_uint(mx));   // pos >= 0
            atomicMax(&g_posmax[1], __float_as_uint(my));
        }
    } else {
        int p = (blockIdx.x - 256) * 256 + threadIdx.x;
        if (p >= NPTS) return;
        int b = p >> 14;
        int seg = (b << 12) + asg[p];
        float2 pp = pos[p];
        atomicAdd(&g_cnt[seg], 1.0f);
        atomicAdd(&g_sumpos[2 * seg], pp.x);
        atomicAdd(&g_sumpos[2 * seg + 1], pp.y);
    }
}

// ---------------- kernel 2: mean pos / scale / start offsets + pad lin_w -----
__global__ void k_mean_wp(float* __restrict__ out, const float* __restrict__ lw) {
    if (blockIdx.x < 128) {
        int i = blockIdx.x * 256 + threadIdx.x;
        float c = g_cnt[i];
        float safe = fmaxf(c, 1.0f);
        float valid = (c > 0.f) ? 1.0f : 0.0f;
        float invmx = 1.0f / __uint_as_float(g_posmax[0]);
        float invmy = 1.0f / __uint_as_float(g_posmax[1]);
        float mx = g_sumpos[2 * i]     * invmx / safe;
        float my = g_sumpos[2 * i + 1] * invmy / safe;
        g_meanpos[2 * i] = mx;
        g_meanpos[2 * i + 1] = my;
        g_scale[i] = valid / safe;
        g_start[i] = atomicAdd(&g_total, (int)c);   // disjoint ranges; order irrelevant
        out[POS_OFF + 2 * i]     = mx * valid;
        out[POS_OFF + 2 * i + 1] = my * valid;
        out[MASK_OFF + i] = valid;
    } else {
        int j = (blockIdx.x - 128) * 256 + threadIdx.x;
        if (j >= NOUT * FP) return;
        int row = j / FP;
        int col = j - row * FP;
        g_Wp[j] = (col < FDIM) ? lw[row * FDIM + col] : 0.0f;
    }
}

// ---------------- kernel 3: bucket point indices by segment ------------------
__global__ void k_sortidx(const int* __restrict__ asg) {
    int p = blockIdx.x * blockDim.x + threadIdx.x;
    if (p >= NPTS) return;
    int b = p >> 14;
    int seg = (b << 12) + asg[p];
    int slot = atomicAdd(&g_fill[seg], 1);
    g_idx[g_start[seg] + slot] = p;
}

// ---------------- kernel 4: warp-per-cluster layernorm gather ----------------
// Accumulates z = (x-mu)*inv per dim over the cluster's points; applies
// w*sum(z) + cnt*b once at the end; plain stores into g_S (incl. zero padding).
__global__ __launch_bounds__(256) void k_gather(
    const float2* __restrict__ pos, const float4* __restrict__ feat4,
    const float* __restrict__ nw, const float* __restrict__ nb)
{
    int w = (blockIdx.x * 256 + threadIdx.x) >> 5;   // cluster id, exact cover
    int lane = threadIdx.x & 31;

    int cnt = (int)g_cnt[w];
    int start = g_start[w];
    float mpx = g_meanpos[2 * w];
    float mpy = g_meanpos[2 * w + 1];
    float invmx = 1.0f / __uint_as_float(g_posmax[0]);
    float invmy = 1.0f / __uint_as_float(g_posmax[1]);

    float acc[8];
#pragma unroll
    for (int q = 0; q < 8; q++) acc[q] = 0.f;
    float arx = 0.f, ary = 0.f;

    for (int j0 = 0; j0 < cnt; j0 += 32) {
        int pj = 0;
        if (j0 + lane < cnt) pj = g_idx[start + j0 + lane];
        int nn = min(32, cnt - j0);
        for (int j = 0; j < nn; j++) {
            int p = __shfl_sync(0xffffffffu, pj, j);
            const float4* fp = feat4 + (size_t)p * 64 + lane * 2;
            float4 f0 = fp[0];
            float4 f1 = fp[1];
            float2 pp = pos[p];                       // broadcast load
            float rx = pp.x * invmx - mpx;
            float ry = pp.y * invmy - mpy;

            float s = f0.x + f0.y + f0.z + f0.w + f1.x + f1.y + f1.z + f1.w;
            float q2 = f0.x * f0.x + f0.y * f0.y + f0.z * f0.z + f0.w * f0.w
                     + f1.x * f1.x + f1.y * f1.y + f1.z * f1.z + f1.w * f1.w;
            if (lane == 0) {
                s += rx + ry;
                q2 += rx * rx + ry * ry;
            }
#pragma unroll
            for (int o = 16; o; o >>= 1) {
                s  += __shfl_xor_sync(0xffffffffu, s, o);
                q2 += __shfl_xor_sync(0xffffffffu, q2, o);
            }
            const float rn = 1.0f / 258.0f;
            float mu = s * rn;
            float var = q2 * rn - mu * mu;
            float inv = rsqrtf(var + 1e-5f);

            acc[0] += (f0.x - mu) * inv;
            acc[1] += (f0.y - mu) * inv;
            acc[2] += (f0.z - mu) * inv;
            acc[3] += (f0.w - mu) * inv;
            acc[4] += (f1.x - mu) * inv;
            acc[5] += (f1.y - mu) * inv;
            acc[6] += (f1.z - mu) * inv;
            acc[7] += (f1.w - mu) * inv;
            if (lane == 0) {
                arx += (rx - mu) * inv;
                ary += (ry - mu) * inv;
            }
        }
    }

    // epilogue: out_d = nw_d * sum(z_d) + cnt * nb_d ; plain stores
    float fcnt = (float)cnt;
    const float4* nw4 = reinterpret_cast<const float4*>(nw);
    const float4* nb4 = reinterpret_cast<const float4*>(nb);
    float4 w0 = nw4[lane * 2], w1 = nw4[lane * 2 + 1];
    float4 b0 = nb4[lane * 2], b1 = nb4[lane * 2 + 1];
    float4 o0, o1;
    o0.x = acc[0] * w0.x + fcnt * b0.x;
    o0.y = acc[1] * w0.y + fcnt * b0.y;
    o0.z = acc[2] * w0.z + fcnt * b0.z;
    o0.w = acc[3] * w0.w + fcnt * b0.w;
    o1.x = acc[4] * w1.x + fcnt * b1.x;
    o1.y = acc[5] * w1.y + fcnt * b1.y;
    o1.z = acc[6] * w1.z + fcnt * b1.z;
    o1.w = acc[7] * w1.w + fcnt * b1.w;

    float* dst = g_S + (size_t)w * FP;
    *reinterpret_cast<float4*>(dst + lane * 8) = o0;
    *reinterpret_cast<float4*>(dst + lane * 8 + 4) = o1;
    if (lane == 0) {
        float2 oR;
        oR.x = arx * nw[256] + fcnt * nb[256];
        oR.y = ary * nw[257] + fcnt * nb[257];
        *reinterpret_cast<float2*>(dst + 256) = oR;
    }
    if (lane < 15) {   // zero padding cols 258..287
        float2 z = make_float2(0.f, 0.f);
        *reinterpret_cast<float2*>(dst + 258 + 2 * lane) = z;
    }
}

// ---------------- kernel 5: tf32 mma.sync GEMM (unchanged, proven) -----------
__global__ __launch_bounds__(256) void k_gemm_mma(float* __restrict__ outfeat) {
    __shared__ uint32_t As[BM * LDA];
    __shared__ uint32_t Bs[BN * LDA];

    const int tid = threadIdx.x;
    const int lane = tid & 31;
    const int warp = tid >> 5;
    const int wm = warp & 3;
    const int wn = warp >> 2;
    const int bm = blockIdx.y * BM;
    const int bn = blockIdx.x * BN;

    const int grow = tid >> 3;
    const int gk4  = tid & 7;

    uint32_t apf[4][4], bpf[4][4];

    auto loadA = [&](int c) {
#pragma unroll
        for (int it = 0; it < 4; it++) {
            int row = grow + it * 32;
            float4 x = *reinterpret_cast<const float4*>(
                g_S + (size_t)(bm + row) * FP + c * BK + gk4 * 4);
            apf[it][0] = f2tf32(x.x); apf[it][1] = f2tf32(x.y);
            apf[it][2] = f2tf32(x.z); apf[it][3] = f2tf32(x.w);
        }
    };
    auto loadB = [&](int c) {
#pragma unroll
        for (int it = 0; it < 4; it++) {
            int row = grow + it * 32;
            float4 x = *reinterpret_cast<const float4*>(
                g_Wp + (size_t)(bn + row) * FP + c * BK + gk4 * 4);
            bpf[it][0] = f2tf32(x.x); bpf[it][1] = f2tf32(x.y);
            bpf[it][2] = f2tf32(x.z); bpf[it][3] = f2tf32(x.w);
        }
    };
    auto stash = [&]() {
#pragma unroll
        for (int it = 0; it < 4; it++) {
            int row = grow + it * 32;
            uint32_t* pa = &As[row * LDA + gk4 * 4];
            pa[0] = apf[it][0]; pa[1] = apf[it][1]; pa[2] = apf[it][2]; pa[3] = apf[it][3];
            uint32_t* pb = &Bs[row * LDA + gk4 * 4];
            pb[0] = bpf[it][0]; pb[1] = bpf[it][1]; pb[2] = bpf[it][2]; pb[3] = bpf[it][3];
        }
    };

    float acc[2][8][4];
#pragma unroll
    for (int mt = 0; mt < 2; mt++)
#pragma unroll
        for (int nt = 0; nt < 8; nt++)
#pragma unroll
            for (int q = 0; q < 4; q++) acc[mt][nt][q] = 0.f;

    loadA(0); loadB(0);
    stash();
    __syncthreads();

    const int qid = lane >> 2;
    const int tig = lane & 3;

    for (int c = 0; c < NCH; c++) {
        if (c + 1 < NCH) { loadA(c + 1); loadB(c + 1); }

#pragma unroll
        for (int k8 = 0; k8 < 4; k8++) {
            const int kb = k8 * 8;
            uint32_t af[2][4];
#pragma unroll
            for (int mt = 0; mt < 2; mt++) {
                int r = wm * 32 + mt * 16 + qid;
                int ci = kb + tig;
                af[mt][0] = As[r * LDA + ci];
                af[mt][1] = As[(r + 8) * LDA + ci];
                af[mt][2] = As[r * LDA + ci + 4];
                af[mt][3] = As[(r + 8) * LDA + ci + 4];
            }
            uint32_t bf[8][2];
#pragma unroll
            for (int nt = 0; nt < 8; nt++) {
                int n = wn * 64 + nt * 8 + qid;
                int kk = kb + tig;
                bf[nt][0] = Bs[n * LDA + kk];
                bf[nt][1] = Bs[n * LDA + kk + 4];
            }
#pragma unroll
            for (int mt = 0; mt < 2; mt++)
#pragma unroll
                for (int nt = 0; nt < 8; nt++) {
                    asm volatile(
                        "mma.sync.aligned.m16n8k8.row.col.f32.tf32.tf32.f32 "
                        "{%0,%1,%2,%3}, {%4,%5,%6,%7}, {%8,%9}, {%0,%1,%2,%3};"
                        : "+f"(acc[mt][nt][0]), "+f"(acc[mt][nt][1]),
                          "+f"(acc[mt][nt][2]), "+f"(acc[mt][nt][3])
                        : "r"(af[mt][0]), "r"(af[mt][1]), "r"(af[mt][2]), "r"(af[mt][3]),
                          "r"(bf[nt][0]), "r"(bf[nt][1]));
                }
        }
        __syncthreads();
        if (c + 1 < NCH) {
            stash();
            __syncthreads();
        }
    }

#pragma unroll
    for (int mt = 0; mt < 2; mt++) {
        int r0 = bm + wm * 32 + mt * 16 + qid;
        float s0 = g_scale[r0];
        float s1 = g_scale[r0 + 8];
        float* row0 = outfeat + (size_t)r0 * NOUT + bn + wn * 64 + tig * 2;
        float* row1 = outfeat + (size_t)(r0 + 8) * NOUT + bn + wn * 64 + tig * 2;
#pragma unroll
        for (int nt = 0; nt < 8; nt++) {
            float2 o0 = make_float2(acc[mt][nt][0] * s0, acc[mt][nt][1] * s0);
            float2 o1 = make_float2(acc[mt][nt][2] * s1, acc[mt][nt][3] * s1);
            *reinterpret_cast<float2*>(row0 + nt * 8) = o0;
            *reinterpret_cast<float2*>(row1 + nt * 8) = o1;
        }
    }
}

// ---------------- launch ------------------------------------------------------
extern "C" void kernel_launch(void* const* d_in, const int* in_sizes, int n_in,
                              void* d_out, int out_size) {
    const float* pos  = (const float*)d_in[0];
    const float* feat = (const float*)d_in[1];
    const int*   asg  = (const int*)d_in[2];
    const float* nw   = (const float*)d_in[3];
    const float* nb   = (const float*)d_in[4];
    const float* lw   = (const float*)d_in[5];
    float* out = (float*)d_out;

    k_zero<<<128, 256>>>();
    k_init<<<256 + NPTS / 256, 256>>>((const float2*)pos, asg);          // 768 blocks
    k_mean_wp<<<128 + (NOUT * FP) / 256, 256>>>(out, lw);                // 704 blocks
    k_sortidx<<<NPTS / 256, 256>>>(asg);
    k_gather<<<MROWS / 8, 256>>>((const float2*)pos, (const float4*)feat, nw, nb);
    dim3 g(NOUT / BN, MROWS / BM);   // (4, 256)
    k_gemm_mma<<<g, 256>>>(out + FEAT_OFF);
}